// round 1
// baseline (speedup 1.0000x reference)
#include <cuda_runtime.h>
#include <math_constants.h>

#define QN 4096
#define VN 2048
#define DN 8192
#define NCHUNK 32
#define RPC 128      /* rows per chunk: QN / NCHUNK */
#define NBANK 64

// accumulator banks: 0=nce_t2v 1=nce_v2t 2=trip_t2v 3=trip_v2t 4=qdl
__device__ double g_bank[5][NBANK];
__device__ float  g_cmax_nce[NCHUNK * VN];
__device__ float  g_csum_nce[NCHUNK * VN];
__device__ float  g_cmax_trip[NCHUNK * VN];

__global__ void k_init() {
    int t = blockIdx.x * blockDim.x + threadIdx.x;
    if (t < 5 * NBANK) ((double*)g_bank)[t] = 0.0;
}

__device__ __forceinline__ float warpMax(float v) {
    #pragma unroll
    for (int o = 16; o; o >>= 1) v = fmaxf(v, __shfl_xor_sync(0xffffffffu, v, o));
    return v;
}
__device__ __forceinline__ float warpSum(float v) {
    #pragma unroll
    for (int o = 16; o; o >>= 1) v += __shfl_xor_sync(0xffffffffu, v, o);
    return v;
}
__device__ __forceinline__ int warpSumI(int v) {
    #pragma unroll
    for (int o = 16; o; o >>= 1) v += __shfl_xor_sync(0xffffffffu, v, o);
    return v;
}

// ---------------------------------------------------------------------------
// QDL: for each of VN pairs (rows 2i, 2i+1 of query_hd), compute
// cos = <a,b>/(||a||·||b||) and 2 * softplus(32*(cos+0.1)).
// One block per pair; streams 2*DN floats (64 KB) per block.
// ---------------------------------------------------------------------------
__global__ void k_qdl(const float* __restrict__ x) {
    int pair = blockIdx.x;
    const float4* A = (const float4*)(x + (size_t)(2 * pair) * DN);
    const float4* B = (const float4*)(x + (size_t)(2 * pair + 1) * DN);
    float sxx = 0.f, syy = 0.f, sxy = 0.f;
    #pragma unroll
    for (int i = 0; i < (DN / 4) / 256; i++) {
        int idx = threadIdx.x + i * 256;
        float4 a = A[idx], b = B[idx];
        sxx += a.x * a.x + a.y * a.y + a.z * a.z + a.w * a.w;
        syy += b.x * b.x + b.y * b.y + b.z * b.z + b.w * b.w;
        sxy += a.x * b.x + a.y * b.y + a.z * b.z + a.w * b.w;
    }
    sxx = warpSum(sxx); syy = warpSum(syy); sxy = warpSum(sxy);
    __shared__ float sh[3][8];
    int w = threadIdx.x >> 5, l = threadIdx.x & 31;
    if (l == 0) { sh[0][w] = sxx; sh[1][w] = syy; sh[2][w] = sxy; }
    __syncthreads();
    if (threadIdx.x == 0) {
        float X = 0.f, Y = 0.f, Z = 0.f;
        #pragma unroll
        for (int i = 0; i < 8; i++) { X += sh[0][i]; Y += sh[1][i]; Z += sh[2][i]; }
        float nx = fmaxf(sqrtf(X), 1e-12f);
        float ny = fmaxf(sqrtf(Y), 1e-12f);
        float c  = Z / (nx * ny);
        float z  = 32.0f * (c + 0.1f);
        float sp = (z > 20.0f) ? z : log1pf(__expf(z));
        atomicAdd(&g_bank[4][pair & (NBANK - 1)], 2.0 * (double)sp);
    }
}

// ---------------------------------------------------------------------------
// NCE t2v: per-row logsumexp of scores_ minus positive. One block per row.
// ---------------------------------------------------------------------------
__global__ void k_nce_row(const float* __restrict__ s, const int* __restrict__ labels) {
    int j = blockIdx.x;
    const float4* row = (const float4*)(s + (size_t)j * VN);
    float4 v0 = row[threadIdx.x];
    float4 v1 = row[threadIdx.x + 256];
    float m = fmaxf(fmaxf(fmaxf(v0.x, v0.y), fmaxf(v0.z, v0.w)),
                    fmaxf(fmaxf(v1.x, v1.y), fmaxf(v1.z, v1.w)));
    m = warpMax(m);
    __shared__ float shm[8], shs[8];
    __shared__ float bM;
    int w = threadIdx.x >> 5, l = threadIdx.x & 31;
    if (l == 0) shm[w] = m;
    __syncthreads();
    if (threadIdx.x == 0) {
        float M = shm[0];
        #pragma unroll
        for (int i = 1; i < 8; i++) M = fmaxf(M, shm[i]);
        bM = M;
    }
    __syncthreads();
    float M = bM;
    float e = __expf(v0.x - M) + __expf(v0.y - M) + __expf(v0.z - M) + __expf(v0.w - M)
            + __expf(v1.x - M) + __expf(v1.y - M) + __expf(v1.z - M) + __expf(v1.w - M);
    e = warpSum(e);
    if (l == 0) shs[w] = e;
    __syncthreads();
    if (threadIdx.x == 0) {
        float S = 0.f;
        #pragma unroll
        for (int i = 0; i < 8; i++) S += shs[i];
        float pos = s[(size_t)j * VN + labels[j]];
        float t2v = M + logf(S) - pos;
        atomicAdd(&g_bank[0][j & (NBANK - 1)], (double)t2v);
    }
}

// ---------------------------------------------------------------------------
// NCE v2t partials: per-column online logsumexp over a 128-row chunk.
// grid (VN/256, NCHUNK), block 256. Coalesced: one thread per column.
// ---------------------------------------------------------------------------
__global__ void k_nce_colpart(const float* __restrict__ s) {
    int col = blockIdx.x * 256 + threadIdx.x;
    int chunk = blockIdx.y;
    const float* p = s + (size_t)(chunk * RPC) * VN + col;
    float m = -CUDART_INF_F, ssum = 0.f;
    for (int r = 0; r < RPC; r += 8) {
        float v[8];
        #pragma unroll
        for (int i = 0; i < 8; i++) v[i] = p[(size_t)(r + i) * VN];
        float cm = v[0];
        #pragma unroll
        for (int i = 1; i < 8; i++) cm = fmaxf(cm, v[i]);
        float nm = fmaxf(m, cm);
        float add = 0.f;
        #pragma unroll
        for (int i = 0; i < 8; i++) add += __expf(v[i] - nm);
        ssum = ssum * __expf(m - nm) + add;   // __expf(-inf)=0 handles first iter
        m = nm;
    }
    g_cmax_nce[chunk * VN + col] = m;
    g_csum_nce[chunk * VN + col] = ssum;
}

__global__ void k_nce_colmerge(const float* __restrict__ s_) {
    int v = blockIdx.x * 256 + threadIdx.x;
    float M = g_cmax_nce[v];
    #pragma unroll
    for (int c = 1; c < NCHUNK; c++) M = fmaxf(M, g_cmax_nce[c * VN + v]);
    float S = 0.f;
    #pragma unroll
    for (int c = 0; c < NCHUNK; c++) S += g_csum_nce[c * VN + v] * __expf(g_cmax_nce[c * VN + v] - M);
    float lse = M + logf(S);
    float a = s_[(size_t)(2 * v) * VN + v];
    float b = s_[(size_t)(2 * v + 1) * VN + v];
    float lse2 = fmaxf(a, b) + log1pf(__expf(-fabsf(a - b)));
    float val = lse - lse2;
    val = warpSum(val);
    __shared__ float sh[8];
    if ((threadIdx.x & 31) == 0) sh[threadIdx.x >> 5] = val;
    __syncthreads();
    if (threadIdx.x == 0) {
        float t = 0.f;
        #pragma unroll
        for (int i = 0; i < 8; i++) t += sh[i];
        atomicAdd(&g_bank[1][blockIdx.x & (NBANK - 1)], (double)t);
    }
}

// ---------------------------------------------------------------------------
// Triplet v2t partials: per-column max over chunk, excluding group rows 2c,2c+1.
// ---------------------------------------------------------------------------
__global__ void k_trip_colpart(const float* __restrict__ s) {
    int col = blockIdx.x * 256 + threadIdx.x;
    int chunk = blockIdx.y;
    int r0 = chunk * RPC;
    const float* p = s + (size_t)r0 * VN + col;
    float m = -CUDART_INF_F;
    for (int r = 0; r < RPC; r += 8) {
        #pragma unroll
        for (int i = 0; i < 8; i++) {
            float v = p[(size_t)(r + i) * VN];
            int gr = r0 + r + i;
            if ((gr >> 1) != col) m = fmaxf(m, v);
        }
    }
    g_cmax_trip[chunk * VN + col] = m;
}

__global__ void k_trip_colmerge(const float* __restrict__ s) {
    int v = blockIdx.x * 256 + threadIdx.x;
    float M = g_cmax_trip[v];
    #pragma unroll
    for (int c = 1; c < NCHUNK; c++) M = fmaxf(M, g_cmax_trip[c * VN + v]);
    float a = s[(size_t)(2 * v) * VN + v];
    float b = s[(size_t)(2 * v + 1) * VN + v];
    float pm = 0.5f * (a + b);
    float loss = fmaxf(0.f, 0.2f + M - pm);
    loss = warpSum(loss);
    __shared__ float sh[8];
    if ((threadIdx.x & 31) == 0) sh[threadIdx.x >> 5] = loss;
    __syncthreads();
    if (threadIdx.x == 0) {
        float t = 0.f;
        #pragma unroll
        for (int i = 0; i < 8; i++) t += sh[i];
        atomicAdd(&g_bank[3][blockIdx.x & (NBANK - 1)], (double)t);
    }
}

// ---------------------------------------------------------------------------
// Triplet t2v: per row, value at descending rank samp=1+rand_idx among the
// masked row (positive -> 999 sits at rank 0). Iterative max-with-multiplicity
// selection (<=20 rounds), exactly matching argsort value semantics under ties.
// ---------------------------------------------------------------------------
__global__ void k_trip_row(const float* __restrict__ s, const int* __restrict__ labels,
                           const int* __restrict__ rand_idx) {
    int j = blockIdx.x;
    const float* row = s + (size_t)j * VN;
    int lab = labels[j];
    const float4* r4 = (const float4*)row;
    float4 a = r4[threadIdx.x];
    float4 b = r4[threadIdx.x + 256];
    float x[8] = { a.x, a.y, a.z, a.w, b.x, b.y, b.z, b.w };
    int base0 = threadIdx.x * 4;
    int base1 = (threadIdx.x + 256) * 4;
    #pragma unroll
    for (int i = 0; i < 4; i++) {
        if (base0 + i == lab) x[i]     = -CUDART_INF_F;  // positive excluded (was 999 @ rank 0)
        if (base1 + i == lab) x[4 + i] = -CUDART_INF_F;
    }
    int samp = 1 + rand_idx[j];
    __shared__ float shf[8];
    __shared__ int   shi[8];
    __shared__ float bm;
    __shared__ int   bc;
    float thr = CUDART_INF_F;
    int rank = 1;
    float ans = 0.f;
    int w = threadIdx.x >> 5, l = threadIdx.x & 31;
    while (true) {
        float m = -CUDART_INF_F;
        #pragma unroll
        for (int i = 0; i < 8; i++) if (x[i] < thr) m = fmaxf(m, x[i]);
        m = warpMax(m);
        if (l == 0) shf[w] = m;
        __syncthreads();
        if (threadIdx.x == 0) {
            float M = shf[0];
            #pragma unroll
            for (int i = 1; i < 8; i++) M = fmaxf(M, shf[i]);
            bm = M;
        }
        __syncthreads();
        m = bm;
        int c = 0;
        #pragma unroll
        for (int i = 0; i < 8; i++) c += (x[i] == m);
        c = warpSumI(c);
        if (l == 0) shi[w] = c;
        __syncthreads();
        if (threadIdx.x == 0) {
            int C = 0;
            #pragma unroll
            for (int i = 0; i < 8; i++) C += shi[i];
            bc = C;
        }
        __syncthreads();
        c = bc;
        if (rank + c > samp) { ans = m; break; }
        rank += c;
        thr = m;
        __syncthreads();
    }
    if (threadIdx.x == 0) {
        float pos = row[lab];
        float loss = fmaxf(0.f, 0.2f + ans - pos);
        atomicAdd(&g_bank[2][j & (NBANK - 1)], (double)loss);
    }
}

// ---------------------------------------------------------------------------
// Final combine.
// ---------------------------------------------------------------------------
__global__ void k_final(float* out) {
    if (threadIdx.x == 0 && blockIdx.x == 0) {
        double a0 = 0, a1 = 0, a2 = 0, a3 = 0, a4 = 0;
        for (int i = 0; i < NBANK; i++) {
            a0 += g_bank[0][i]; a1 += g_bank[1][i]; a2 += g_bank[2][i];
            a3 += g_bank[3][i]; a4 += g_bank[4][i];
        }
        double total = 0.02 * (a0 / QN + a1 / VN)
                     + (a2 / QN + a3 / VN)
                     + 0.04 * (a4 / QN);
        out[0] = (float)total;
    }
}

extern "C" void kernel_launch(void* const* d_in, const int* in_sizes, int n_in,
                              void* d_out, int out_size) {
    const float* scores   = (const float*)d_in[0];   // hd_similarity_scores  [Q,V]
    const float* scores_  = (const float*)d_in[1];   // hd_similarity_scores_ [Q,V]
    const float* qhd      = (const float*)d_in[2];   // query_hd [Q,D]
    const int*   labels   = (const int*)d_in[3];
    const int*   rand_idx = (const int*)d_in[4];
    float* out = (float*)d_out;

    k_init<<<1, 5 * NBANK>>>();
    k_qdl<<<VN, 256>>>(qhd);
    k_nce_row<<<QN, 256>>>(scores_, labels);
    k_nce_colpart<<<dim3(VN / 256, NCHUNK), 256>>>(scores_);
    k_nce_colmerge<<<VN / 256, 256>>>(scores_);
    k_trip_colpart<<<dim3(VN / 256, NCHUNK), 256>>>(scores);
    k_trip_colmerge<<<VN / 256, 256>>>(scores);
    k_trip_row<<<QN, 256>>>(scores, labels, rand_idx);
    k_final<<<1, 1>>>(out);
}